// round 1
// baseline (speedup 1.0000x reference)
#include <cuda_runtime.h>
#include <math.h>

// ---------------------------------------------------------------------------
// Scratch (device globals; no allocation anywhere)
// ---------------------------------------------------------------------------
static __device__ float g_bufA[33554432];   // 134 MB: h1 / h3 / zq / g2
static __device__ float g_bufB[16777216];   //  67 MB: h2 / z  / g1 / g3
static __device__ int   g_idx[8192];
static __device__ float g_e2[1024];

#define CK  8
#define TW  16
#define TH  8
#define COT 32

// ---------------------------------------------------------------------------
// Encoder conv: k=4, s=2, p=1, ReLU.  in NCHW, w OIHW.
// Block: 256 thr. Tile: 16x8 outputs x 32 couts. Thread: 2x2 spatial x 4 cout.
// ---------------------------------------------------------------------------
__global__ __launch_bounds__(256)
void conv_enc_kernel(const float* __restrict__ in, const float* __restrict__ w,
                     const float* __restrict__ bias, float* __restrict__ out,
                     int Cin, int Hin, int Win, int Cout)
{
    const int Hout = Hin >> 1, Wout = Win >> 1;
    const int tiles_x = Wout / TW;
    const int tx = blockIdx.x % tiles_x;
    const int ty = blockIdx.x / tiles_x;
    const int oy0 = ty * TH, ox0 = tx * TW;
    const int co0 = blockIdx.y * COT;
    const int b   = blockIdx.z;

    const int PR = 2*TH + 2;   // 18 patch rows
    const int PC = 2*TW + 2;   // 34 patch cols
    const int P  = 36;         // pitch
    __shared__ float in_s[CK][PR][P];
    __shared__ __align__(16) float w_s[CK][16][COT];

    const int tid  = threadIdx.x;
    const int cg   = tid >> 5;          // 0..7 cout group
    const int lane = tid & 31;
    const int sx   = lane & 7;          // col sub-tile
    const int sy   = lane >> 3;         // row sub-tile (0..3)

    float acc[2][2][4];
    #pragma unroll
    for (int i = 0; i < 2; i++)
        #pragma unroll
        for (int j = 0; j < 2; j++)
            #pragma unroll
            for (int c = 0; c < 4; c++) acc[i][j][c] = 0.f;

    const int  iy_org = 2*oy0 - 1;
    const int  ix_org = 2*ox0 - 1;
    const long inB = (long)b * Cin * Hin * Win;

    for (int ci0 = 0; ci0 < Cin; ci0 += CK) {
        __syncthreads();
        // input patch (zero-fill OOB + tail channels)
        for (int idx = tid; idx < CK*PR*PC; idx += 256) {
            int c  = idx % PC;
            int r  = (idx / PC) % PR;
            int ci = idx / (PC*PR);
            int iy = iy_org + r, ix = ix_org + c;
            int cig = ci0 + ci;
            float v = 0.f;
            if (cig < Cin && iy >= 0 && iy < Hin && ix >= 0 && ix < Win)
                v = in[inB + ((long)cig*Hin + iy)*Win + ix];
            in_s[ci][r][c] = v;
        }
        // weights: w[(co0+cl)*Cin*16 + cig*16 + t] -> w_s[ci][t][cl]
        for (int idx = tid; idx < CK*16*COT; idx += 256) {
            int cl = idx % COT;
            int t  = (idx / COT) % 16;
            int ci = idx / (COT*16);
            int cig = ci0 + ci;
            float v = 0.f;
            if (cig < Cin)
                v = w[((long)(co0+cl)*Cin + cig)*16 + t];
            w_s[ci][t][cl] = v;
        }
        __syncthreads();

        #pragma unroll 1
        for (int ci = 0; ci < CK; ci++) {
            #pragma unroll
            for (int t = 0; t < 16; t++) {
                const int ky = t >> 2, kx = t & 3;
                float4 wv = *reinterpret_cast<const float4*>(&w_s[ci][t][cg*4]);
                #pragma unroll
                for (int dy = 0; dy < 2; dy++) {
                    #pragma unroll
                    for (int dx = 0; dx < 2; dx++) {
                        float a = in_s[ci][4*sy + 2*dy + ky][4*sx + 2*dx + kx];
                        acc[dy][dx][0] += a * wv.x;
                        acc[dy][dx][1] += a * wv.y;
                        acc[dy][dx][2] += a * wv.z;
                        acc[dy][dx][3] += a * wv.w;
                    }
                }
            }
        }
    }

    const long outB = (long)b * Cout * Hout * Wout;
    #pragma unroll
    for (int c = 0; c < 4; c++) {
        int co = co0 + cg*4 + c;
        float bv = bias[co];
        #pragma unroll
        for (int dy = 0; dy < 2; dy++) {
            int oy = oy0 + 2*sy + dy;
            #pragma unroll
            for (int dx = 0; dx < 2; dx++) {
                int ox = ox0 + 2*sx + dx;
                float v = fmaxf(acc[dy][dx][c] + bv, 0.f);
                out[outB + ((long)co*Hout + oy)*Wout + ox] = v;
            }
        }
    }
}

// ---------------------------------------------------------------------------
// ConvTranspose: k=4, s=2, p=1, ReLU.  out[oy] gets in[iy] taps with
// oy = 2*iy - 1 + ky.  w layout (Cin, Cout, 4, 4).
// Thread owns a same-parity 2x2 output quad -> shared tap set (2B/FFMA).
// ---------------------------------------------------------------------------
__global__ __launch_bounds__(256)
void convt_kernel(const float* __restrict__ in, const float* __restrict__ w,
                  const float* __restrict__ bias, float* __restrict__ out,
                  int Cin, int Hin, int Win, int Cout)
{
    const int Hout = Hin*2, Wout = Win*2;
    const int tiles_x = Wout / TW;
    const int tx = blockIdx.x % tiles_x;
    const int ty = blockIdx.x / tiles_x;
    const int oy0 = ty*TH, ox0 = tx*TW;
    const int co0 = blockIdx.y * COT;
    const int b   = blockIdx.z;

    const int PR = TH/2 + 2;   // 6
    const int PC = TW/2 + 2;   // 10
    const int P  = 12;
    __shared__ float in_s[CK][PR][P];
    __shared__ __align__(16) float w_s[CK][16][COT];

    const int tid  = threadIdx.x;
    const int cg   = tid >> 5;
    const int lane = tid & 31;
    const int px = lane & 1;
    const int py = (lane >> 1) & 1;
    const int sx = (lane >> 2) & 3;   // 0..3  (4-col groups)
    const int sy = (lane >> 4) & 1;   // 0..1  (4-row groups)

    const int ky0 = py ^ 1;           // valid ky: {ky0, ky0+2}
    const int kx0 = px ^ 1;
    // patch-local base index: iyl = base_y + dy - kyi, ixl = base_x + dx - kxi
    const int base_y = (4*sy + py + 1 - ky0)/2 + 1;
    const int base_x = (4*sx + px + 1 - kx0)/2 + 1;

    float acc[2][2][4];
    #pragma unroll
    for (int i = 0; i < 2; i++)
        #pragma unroll
        for (int j = 0; j < 2; j++)
            #pragma unroll
            for (int c = 0; c < 4; c++) acc[i][j][c] = 0.f;

    const int  iy0b = oy0/2 - 1;
    const int  ix0b = ox0/2 - 1;
    const long inB = (long)b * Cin * Hin * Win;

    for (int ci0 = 0; ci0 < Cin; ci0 += CK) {
        __syncthreads();
        for (int idx = tid; idx < CK*PR*PC; idx += 256) {
            int c  = idx % PC;
            int r  = (idx / PC) % PR;
            int ci = idx / (PC*PR);
            int iy = iy0b + r, ix = ix0b + c;
            int cig = ci0 + ci;
            float v = 0.f;
            if (cig < Cin && iy >= 0 && iy < Hin && ix >= 0 && ix < Win)
                v = in[inB + ((long)cig*Hin + iy)*Win + ix];
            in_s[ci][r][c] = v;
        }
        // w[(cig)*Cout*16 + (co0+cl)*16 + t] -> w_s[ci][t][cl]
        for (int idx = tid; idx < CK*16*COT; idx += 256) {
            int cl = idx % COT;
            int t  = (idx / COT) % 16;
            int ci = idx / (COT*16);
            int cig = ci0 + ci;
            float v = 0.f;
            if (cig < Cin)
                v = w[((long)cig*Cout + (co0+cl))*16 + t];
            w_s[ci][t][cl] = v;
        }
        __syncthreads();

        #pragma unroll 1
        for (int ci = 0; ci < CK; ci++) {
            #pragma unroll
            for (int kyi = 0; kyi < 2; kyi++) {
                #pragma unroll
                for (int kxi = 0; kxi < 2; kxi++) {
                    const int ky = ky0 + 2*kyi, kx = kx0 + 2*kxi;
                    const int t  = ky*4 + kx;
                    float4 wv = *reinterpret_cast<const float4*>(&w_s[ci][t][cg*4]);
                    #pragma unroll
                    for (int dy = 0; dy < 2; dy++) {
                        #pragma unroll
                        for (int dx = 0; dx < 2; dx++) {
                            float a = in_s[ci][base_y + dy - kyi][base_x + dx - kxi];
                            acc[dy][dx][0] += a * wv.x;
                            acc[dy][dx][1] += a * wv.y;
                            acc[dy][dx][2] += a * wv.z;
                            acc[dy][dx][3] += a * wv.w;
                        }
                    }
                }
            }
        }
    }

    const long outB = (long)b * Cout * Hout * Wout;
    #pragma unroll
    for (int c = 0; c < 4; c++) {
        int co = co0 + cg*4 + c;
        float bv = bias[co];
        #pragma unroll
        for (int dy = 0; dy < 2; dy++) {
            int oy = oy0 + 4*sy + py + 2*dy;
            #pragma unroll
            for (int dx = 0; dx < 2; dx++) {
                int ox = ox0 + 4*sx + px + 2*dx;
                float v = fmaxf(acc[dy][dx][c] + bv, 0.f);
                out[outB + ((long)co*Hout + oy)*Wout + ox] = v;
            }
        }
    }
}

// ---------------------------------------------------------------------------
// Final ConvT layer: Cin=32, Cout=3, tanh.  One thread per output pixel.
// ---------------------------------------------------------------------------
__global__ __launch_bounds__(256)
void convt_final_kernel(const float* __restrict__ in, const float* __restrict__ w,
                        const float* __restrict__ bias, float* __restrict__ out)
{
    const int Cin = 32, Hin = 128, Win = 128, Cout = 3, Hout = 256, Wout = 256;
    __shared__ float w_s[32][3][16];
    const int tid = threadIdx.x;
    for (int i = tid; i < 32*3*16; i += 256)
        ((float*)w_s)[i] = w[i];
    __syncthreads();

    const int b = blockIdx.z;
    const int tiles_x = Wout / 16;             // 16
    const int tx = blockIdx.x % tiles_x;
    const int ty = blockIdx.x / tiles_x;
    const int ox = tx*16 + (tid & 15);
    const int oy = ty*16 + (tid >> 4);

    const int ky0 = (oy + 1) & 1;
    const int kx0 = (ox + 1) & 1;

    float a0 = bias[0], a1 = bias[1], a2 = bias[2];
    const float* inb = in + (long)b * Cin * Hin * Win;

    #pragma unroll
    for (int kyi = 0; kyi < 2; kyi++) {
        #pragma unroll
        for (int kxi = 0; kxi < 2; kxi++) {
            const int ky = ky0 + 2*kyi, kx = kx0 + 2*kxi;
            const int iy = (oy + 1 - ky) / 2;
            const int ix = (ox + 1 - kx) / 2;
            if (iy < 0 || iy >= Hin || ix < 0 || ix >= Win) continue;
            const int t = ky*4 + kx;
            const float* ip = inb + (long)iy*Win + ix;
            #pragma unroll 4
            for (int ci = 0; ci < 32; ci++) {
                float v = ip[(long)ci * Hin * Win];
                a0 += v * w_s[ci][0][t];
                a1 += v * w_s[ci][1][t];
                a2 += v * w_s[ci][2][t];
            }
        }
    }
    const long o = (long)b * Cout * Hout * Wout + (long)oy * Wout + ox;
    out[o]                        = tanhf(a0);
    out[o + (long)Hout*Wout]      = tanhf(a1);
    out[o + 2L*Hout*Wout]         = tanhf(a2);
}

// ---------------------------------------------------------------------------
// Quantizer
// ---------------------------------------------------------------------------
__global__ void e2_kernel(const float* __restrict__ embed, float* __restrict__ e2)
{
    int k = blockIdx.x * blockDim.x + threadIdx.x;
    if (k >= 1024) return;
    const float* e = embed + (long)k * 512;
    float s = 0.f;
    #pragma unroll 4
    for (int d = 0; d < 512; d++) { float v = e[d]; s += v * v; }
    e2[k] = s;
}

__global__ __launch_bounds__(128)
void argmin_kernel(const float* __restrict__ z, const float* __restrict__ embed,
                   const float* __restrict__ e2, int* __restrict__ idx_out)
{
    __shared__ float z_s[512][8];
    __shared__ float rv[8][128];
    __shared__ int   ri[8][128];
    const int tid = threadIdx.x;
    const int n0 = blockIdx.x * 8;              // 1024 blocks
    const int b = n0 >> 8;
    const int pix0 = n0 & 255;
    const float* zb = z + (long)b * 512 * 256 + pix0;

    for (int i = tid; i < 512*8; i += 128) {
        int d = i >> 3, nl = i & 7;
        z_s[d][nl] = zb[(long)d * 256 + nl];
    }
    __syncthreads();

    float bv[8]; int bi[8];
    #pragma unroll
    for (int nl = 0; nl < 8; nl++) { bv[nl] = 3.4e38f; bi[nl] = 0; }

    for (int k = tid; k < 1024; k += 128) {
        const float* e = embed + (long)k * 512;
        float dot[8];
        #pragma unroll
        for (int nl = 0; nl < 8; nl++) dot[nl] = 0.f;
        #pragma unroll 4
        for (int d = 0; d < 512; d++) {
            float ev = e[d];
            #pragma unroll
            for (int nl = 0; nl < 8; nl++) dot[nl] += ev * z_s[d][nl];
        }
        float c = e2[k];
        #pragma unroll
        for (int nl = 0; nl < 8; nl++) {
            float dist = c - 2.f * dot[nl];
            if (dist < bv[nl]) { bv[nl] = dist; bi[nl] = k; }  // k increasing -> first-min kept
        }
    }
    #pragma unroll
    for (int nl = 0; nl < 8; nl++) { rv[nl][tid] = bv[nl]; ri[nl][tid] = bi[nl]; }
    __syncthreads();
    if (tid < 8) {
        float best = rv[tid][0]; int besti = ri[tid][0];
        for (int j = 1; j < 128; j++) {
            float v = rv[tid][j]; int ii = ri[tid][j];
            if (v < best || (v == best && ii < besti)) { best = v; besti = ii; }
        }
        idx_out[n0 + tid] = besti;
    }
}

__global__ void gather_kernel(const int* __restrict__ idx, const float* __restrict__ embed,
                              float* __restrict__ zq)
{
    const int n = blockIdx.x;                   // 8192
    const int b = n >> 8, pix = n & 255;
    const float* e = embed + (long)idx[n] * 512;
    float* o = zq + (long)b * 512 * 256 + pix;
    for (int d = threadIdx.x; d < 512; d += 256)
        o[(long)d * 256] = e[d];
}

// ---------------------------------------------------------------------------
// Launch
// ---------------------------------------------------------------------------
extern "C" void kernel_launch(void* const* d_in, const int* in_sizes, int n_in,
                              void* d_out, int out_size)
{
    const float* x     = (const float*)d_in[0];
    const float* ew1   = (const float*)d_in[1];
    const float* eb1   = (const float*)d_in[2];
    const float* ew2   = (const float*)d_in[3];
    const float* eb2   = (const float*)d_in[4];
    const float* ew3   = (const float*)d_in[5];
    const float* eb3   = (const float*)d_in[6];
    const float* ew4   = (const float*)d_in[7];
    const float* eb4   = (const float*)d_in[8];
    const float* dw1   = (const float*)d_in[9];
    const float* db1   = (const float*)d_in[10];
    const float* dw2   = (const float*)d_in[11];
    const float* db2   = (const float*)d_in[12];
    const float* dw3   = (const float*)d_in[13];
    const float* db3   = (const float*)d_in[14];
    const float* dw4   = (const float*)d_in[15];
    const float* db4   = (const float*)d_in[16];
    const float* embed = (const float*)d_in[17];
    float* out = (float*)d_out;

    float *A, *B, *e2p; int* idxp;
    cudaGetSymbolAddress((void**)&A,    g_bufA);
    cudaGetSymbolAddress((void**)&B,    g_bufB);
    cudaGetSymbolAddress((void**)&e2p,  g_e2);
    cudaGetSymbolAddress((void**)&idxp, g_idx);

    const int NB = 32;

    // ---- encoder ----
    // e1: (3,256,256) -> (64,128,128)  tiles: (128/16)*(128/8)=128
    conv_enc_kernel<<<dim3(128, 64/COT, NB), 256>>>(x,  ew1, eb1, A, 3,   256, 256, 64);
    // e2: (64,128,128) -> (128,64,64)
    conv_enc_kernel<<<dim3(32, 128/COT, NB), 256>>>(A,  ew2, eb2, B, 64,  128, 128, 128);
    // e3: (128,64,64) -> (256,32,32)
    conv_enc_kernel<<<dim3(8,  256/COT, NB), 256>>>(B,  ew3, eb3, A, 128, 64,  64,  256);
    // e4: (256,32,32) -> (512,16,16)   z in B
    conv_enc_kernel<<<dim3(2,  512/COT, NB), 256>>>(A,  ew4, eb4, B, 256, 32,  32,  512);

    // ---- quantizer ----
    e2_kernel<<<4, 256>>>(embed, e2p);
    argmin_kernel<<<1024, 128>>>(B, embed, e2p, idxp);
    gather_kernel<<<8192, 256>>>(idxp, embed, A);          // zq in A

    // ---- decoder ----
    // d1: (512,16,16) -> (128,32,32)   tiles: (32/16)*(32/8)=8
    convt_kernel<<<dim3(8,   128/COT, NB), 256>>>(A, dw1, db1, B, 512, 16,  16,  128);
    // d2: (128,32,32) -> (64,64,64)
    convt_kernel<<<dim3(32,  64/COT,  NB), 256>>>(B, dw2, db2, A, 128, 32,  32,  64);
    // d3: (64,64,64) -> (32,128,128)
    convt_kernel<<<dim3(128, 32/COT,  NB), 256>>>(A, dw3, db3, B, 64,  64,  64,  32);
    // d4: (32,128,128) -> (3,256,256) + tanh
    convt_final_kernel<<<dim3(256, 1, NB), 256>>>(B, dw4, db4, out);
}

// round 2
// speedup vs baseline: 1.2108x; 1.2108x over previous
#include <cuda_runtime.h>
#include <math.h>

// ---------------------------------------------------------------------------
// Scratch (device globals; no allocation anywhere)
// ---------------------------------------------------------------------------
static __device__ float g_bufA[33554432];   // 134 MB
static __device__ float g_bufB[16777216];   //  67 MB
static __device__ int   g_idx[8192];
static __device__ float g_e2[1024];

__device__ __forceinline__ void fma4(float* acc, float a, float4 w) {
    acc[0] += a * w.x; acc[1] += a * w.y; acc[2] += a * w.z; acc[3] += a * w.w;
}

// ---------------------------------------------------------------------------
// Encoder conv: k=4, s=2, p=1, ReLU.  in NCHW, w OIHW.
// Block 256 thr = 8 warps x 4 couts (32 couts). Lane owns one output column,
// RPT=4 output rows. Input patch de-interleaved into even/odd column planes
// so all activation LDS are stride-1 conflict-free. Weight LDS are warp-
// broadcast (all lanes in a warp share the cout group).
// ---------------------------------------------------------------------------
template<int TW, int TH, int CK>
__global__ __launch_bounds__(256)
void conv_enc(const float* __restrict__ in, const float* __restrict__ w,
              const float* __restrict__ bias, float* __restrict__ out,
              int Cin, int Hin, int Win, int Cout)
{
    constexpr int RG  = 32 / TW;        // row groups per warp
    constexpr int RPT = TH / RG;        // output rows per thread (=4)
    constexpr int IR  = 2 * TH + 2;     // input patch rows
    constexpr int HC  = TW + 1;         // half-cols per parity plane
    constexpr int HCP = (TW == 16) ? 18 : 33;  // pitch (bank-conflict-free)
    constexpr int TC  = 2 * TW + 2;     // input patch cols

    __shared__ float ev_s[CK][IR][HCP];
    __shared__ float od_s[CK][IR][HCP];
    __shared__ __align__(16) float w_s[CK][16][32];

    const int Hout = Hin >> 1, Wout = Win >> 1;
    const int tiles_x = Wout / TW;
    const int tx = blockIdx.x % tiles_x;
    const int ty = blockIdx.x / tiles_x;
    const int oy0 = ty * TH, ox0 = tx * TW;
    const int co0 = blockIdx.y * 32;
    const int b   = blockIdx.z;

    const int tid  = threadIdx.x;
    const int cg   = tid >> 5;               // warp = cout group
    const int lane = tid & 31;
    const int colx = lane % TW;
    const int rg   = lane / TW;
    const int cg4  = cg * 4;
    const int rbase = 2 * rg * RPT;

    float acc[RPT][4];
    #pragma unroll
    for (int i = 0; i < RPT; i++)
        #pragma unroll
        for (int c = 0; c < 4; c++) acc[i][c] = 0.f;

    const int  iy_org = 2 * oy0 - 1;
    const int  ix_org = 2 * ox0 - 1;
    const long inB = (long)b * Cin * Hin * Win;

    for (int ci0 = 0; ci0 < Cin; ci0 += CK) {
        __syncthreads();
        // ---- input patch (deinterleaved, zero-filled OOB) ----
        for (int idx = tid; idx < CK * IR * TC; idx += 256) {
            int j  = idx % TC;
            int r  = (idx / TC) % IR;
            int ci = idx / (TC * IR);
            int iy = iy_org + r, ix = ix_org + j;
            int cig = ci0 + ci;
            float v = 0.f;
            if (cig < Cin && iy >= 0 && iy < Hin && ix >= 0 && ix < Win)
                v = in[inB + ((long)cig * Hin + iy) * Win + ix];
            if (j & 1) od_s[ci][r][j >> 1] = v;
            else       ev_s[ci][r][j >> 1] = v;
        }
        // ---- weights ----
        for (int idx = tid; idx < CK * 16 * 32; idx += 256) {
            int cl = idx & 31;
            int t  = (idx >> 5) & 15;
            int ci = idx >> 9;
            int cig = ci0 + ci;
            float v = 0.f;
            if (cig < Cin)
                v = w[((long)(co0 + cl) * Cin + cig) * 16 + t];
            w_s[ci][t][cl] = v;
        }
        __syncthreads();

        #pragma unroll 1
        for (int ci = 0; ci < CK; ci++) {
            #pragma unroll
            for (int q = 0; q < 2; q++) {       // row parity; ky in {q, q+2}
                float4 w0[4], w2[4];
                #pragma unroll
                for (int kx = 0; kx < 4; kx++) {
                    w0[kx] = *reinterpret_cast<const float4*>(&w_s[ci][ q      * 4 + kx][cg4]);
                    w2[kx] = *reinterpret_cast<const float4*>(&w_s[ci][(q + 2) * 4 + kx][cg4]);
                }
                #pragma unroll
                for (int j = 0; j <= RPT; j++) {
                    const int r = rbase + 2 * j + q;
                    float ae0 = ev_s[ci][r][colx];
                    float ao0 = od_s[ci][r][colx];
                    float ae1 = ev_s[ci][r][colx + 1];
                    float ao1 = od_s[ci][r][colx + 1];
                    if (j < RPT) {              // ky = q, output row j
                        fma4(acc[j], ae0, w0[0]); fma4(acc[j], ao0, w0[1]);
                        fma4(acc[j], ae1, w0[2]); fma4(acc[j], ao1, w0[3]);
                    }
                    if (j > 0) {                // ky = q+2, output row j-1
                        fma4(acc[j-1], ae0, w2[0]); fma4(acc[j-1], ao0, w2[1]);
                        fma4(acc[j-1], ae1, w2[2]); fma4(acc[j-1], ao1, w2[3]);
                    }
                }
            }
        }
    }

    const long outB = (long)b * Cout * Hout * Wout;
    const int  ox = ox0 + colx;
    #pragma unroll
    for (int c = 0; c < 4; c++) {
        const int co = co0 + cg4 + c;
        const float bv = bias[co];
        #pragma unroll
        for (int i = 0; i < RPT; i++) {
            const int oy = oy0 + rg * RPT + i;
            out[outB + ((long)co * Hout + oy) * Wout + ox] = fmaxf(acc[i][c] + bv, 0.f);
        }
    }
}

// ---------------------------------------------------------------------------
// ConvTranspose: k=4, s=2, p=1, ReLU. w layout (Cin, Cout, 4, 4).
// oy = 2*iy - 1 + ky. Lane owns one INPUT column (2 output cols), 2 input
// rows (4 output rows). 4 parity sub-convolutions; activation loads stride-1.
// ---------------------------------------------------------------------------
template<int TWI, int CK>
__global__ __launch_bounds__(256)
void convt(const float* __restrict__ in, const float* __restrict__ w,
           const float* __restrict__ bias, float* __restrict__ out,
           int Cin, int Hin, int Win, int Cout)
{
    constexpr int PRT  = 2;                 // input rows per thread
    constexpr int RGI  = 32 / TWI;
    constexpr int BIR  = PRT * RGI;         // block input rows
    constexpr int PIR  = BIR + 2;           // patch rows (halo)
    constexpr int PIC  = TWI + 2;           // patch cols
    constexpr int PICP = (TWI == 16) ? 24 : 35; // pitch (conflict-free)

    __shared__ float in_s[CK][PIR][PICP];
    __shared__ __align__(16) float w_s[CK][16][32];

    const int Hout = Hin * 2, Wout = Win * 2;
    const int colb = Win / TWI;
    const int tx = blockIdx.x % colb;
    const int ry = blockIdx.x / colb;
    const int Rbase = ry * BIR;
    const int c0 = tx * TWI;
    const int co0 = blockIdx.y * 32;
    const int b   = blockIdx.z;

    const int tid  = threadIdx.x;
    const int cg   = tid >> 5;
    const int lane = tid & 31;
    const int cI   = lane % TWI;
    const int rgI  = lane / TWI;
    const int cg4  = cg * 4;
    const int prbase = rgI * PRT;
    const int pcol = cI + 1;

    float acc[2][2][2][4];                  // [iR][py][px][c]
    #pragma unroll
    for (int i = 0; i < 2; i++)
        #pragma unroll
        for (int p = 0; p < 2; p++)
            #pragma unroll
            for (int q = 0; q < 2; q++)
                #pragma unroll
                for (int c = 0; c < 4; c++) acc[i][p][q][c] = 0.f;

    const long inB = (long)b * Cin * Hin * Win;

    for (int ci0 = 0; ci0 < Cin; ci0 += CK) {
        __syncthreads();
        for (int idx = tid; idx < CK * PIR * PIC; idx += 256) {
            int j  = idx % PIC;
            int pr = (idx / PIC) % PIR;
            int ci = idx / (PIC * PIR);
            int iy = Rbase - 1 + pr, ix = c0 - 1 + j;
            int cig = ci0 + ci;
            float v = 0.f;
            if (cig < Cin && iy >= 0 && iy < Hin && ix >= 0 && ix < Win)
                v = in[inB + ((long)cig * Hin + iy) * Win + ix];
            in_s[ci][pr][j] = v;
        }
        for (int idx = tid; idx < CK * 16 * 32; idx += 256) {
            int cl = idx & 31;
            int t  = (idx >> 5) & 15;
            int ci = idx >> 9;
            int cig = ci0 + ci;
            float v = 0.f;
            if (cig < Cin)
                v = w[((long)cig * Cout + (co0 + cl)) * 16 + t];
            w_s[ci][t][cl] = v;
        }
        __syncthreads();

        #pragma unroll 1
        for (int ci = 0; ci < CK; ci++) {
            #pragma unroll
            for (int px = 0; px < 2; px++) {
                float4 wk[4][2];            // [ky][kxi], kx = (px^1) + 2*kxi
                #pragma unroll
                for (int ky = 0; ky < 4; ky++)
                    #pragma unroll
                    for (int kxi = 0; kxi < 2; kxi++)
                        wk[ky][kxi] = *reinterpret_cast<const float4*>(
                            &w_s[ci][ky * 4 + (px ^ 1) + 2 * kxi][cg4]);
                const int ca = pcol + px;       // kxi=0
                const int cb = pcol + px - 1;   // kxi=1
                #pragma unroll
                for (int jr = 0; jr < 4; jr++) {
                    const int pr = prbase + jr;
                    float a0 = in_s[ci][pr][ca];
                    float a1 = in_s[ci][pr][cb];
                    // iy == R   (jr-1): py=0 ky=1; py=1 ky=2
                    if (jr >= 1 && jr <= 2) {
                        fma4(acc[jr-1][0][px], a0, wk[1][0]); fma4(acc[jr-1][0][px], a1, wk[1][1]);
                        fma4(acc[jr-1][1][px], a0, wk[2][0]); fma4(acc[jr-1][1][px], a1, wk[2][1]);
                    }
                    // iy == R-1 (jr):   py=0 ky=3
                    if (jr < 2) {
                        fma4(acc[jr][0][px], a0, wk[3][0]); fma4(acc[jr][0][px], a1, wk[3][1]);
                    }
                    // iy == R+1 (jr-2): py=1 ky=0
                    if (jr >= 2) {
                        fma4(acc[jr-2][1][px], a0, wk[0][0]); fma4(acc[jr-2][1][px], a1, wk[0][1]);
                    }
                }
            }
        }
    }

    const long outB = (long)b * Cout * Hout * Wout;
    const int  oxp = 2 * (c0 + cI);
    #pragma unroll
    for (int c = 0; c < 4; c++) {
        const int co = co0 + cg4 + c;
        const float bv = bias[co];
        #pragma unroll
        for (int iR = 0; iR < 2; iR++) {
            #pragma unroll
            for (int py = 0; py < 2; py++) {
                const int oy = 2 * (Rbase + prbase + iR) + py;
                float2 v;
                v.x = fmaxf(acc[iR][py][0][c] + bv, 0.f);
                v.y = fmaxf(acc[iR][py][1][c] + bv, 0.f);
                *reinterpret_cast<float2*>(&out[outB + ((long)co * Hout + oy) * Wout + oxp]) = v;
            }
        }
    }
}

// ---------------------------------------------------------------------------
// Final ConvT layer: Cin=32, Cout=3, tanh. smem input tile + smem weights.
// ---------------------------------------------------------------------------
__global__ __launch_bounds__(256)
void convt_final_kernel(const float* __restrict__ in, const float* __restrict__ w,
                        const float* __restrict__ bias, float* __restrict__ out)
{
    const int Cin = 32, Hin = 128, Win = 128, Hout = 256, Wout = 256;
    __shared__ float in_s[32][10][11];
    __shared__ float w_s[32][3][16];

    const int tid = threadIdx.x;
    const int b = blockIdx.z;
    const int tx = blockIdx.x & 15;
    const int ty = blockIdx.x >> 4;
    const int oy0 = ty * 16, ox0 = tx * 16;
    const int iyb = oy0 / 2 - 1, ixb = ox0 / 2 - 1;

    for (int i = tid; i < 32 * 3 * 16; i += 256)
        ((float*)w_s)[i] = w[i];
    const float* inb = in + (long)b * Cin * Hin * Win;
    for (int idx = tid; idx < 3200; idx += 256) {
        int c  = idx % 10;
        int r  = (idx / 10) % 10;
        int ci = idx / 100;
        int iy = iyb + r, ix = ixb + c;
        float v = 0.f;
        if (iy >= 0 && iy < Hin && ix >= 0 && ix < Win)
            v = inb[((long)ci * Hin + iy) * Win + ix];
        in_s[ci][r][c] = v;
    }
    __syncthreads();

    const int ox = ox0 + (tid & 15);
    const int oy = oy0 + (tid >> 4);
    const int ky0 = (oy + 1) & 1;
    const int kx0 = (ox + 1) & 1;

    float a0 = bias[0], a1 = bias[1], a2 = bias[2];
    #pragma unroll
    for (int kyi = 0; kyi < 2; kyi++) {
        #pragma unroll
        for (int kxi = 0; kxi < 2; kxi++) {
            const int ky = ky0 + 2 * kyi, kx = kx0 + 2 * kxi;
            const int pr = (oy + 1 - ky) / 2 - iyb;
            const int pc = (ox + 1 - kx) / 2 - ixb;
            const int t = ky * 4 + kx;
            #pragma unroll 8
            for (int ci = 0; ci < 32; ci++) {
                float v = in_s[ci][pr][pc];
                a0 += v * w_s[ci][0][t];
                a1 += v * w_s[ci][1][t];
                a2 += v * w_s[ci][2][t];
            }
        }
    }
    const long o = (long)b * 3 * Hout * Wout + (long)oy * Wout + ox;
    out[o]                    = tanhf(a0);
    out[o + (long)Hout*Wout]  = tanhf(a1);
    out[o + 2L*Hout*Wout]     = tanhf(a2);
}

// ---------------------------------------------------------------------------
// Quantizer
// ---------------------------------------------------------------------------
__global__ void e2_kernel(const float* __restrict__ embed, float* __restrict__ e2)
{
    int k = blockIdx.x * blockDim.x + threadIdx.x;
    if (k >= 1024) return;
    const float* e = embed + (long)k * 512;
    float s = 0.f;
    #pragma unroll 4
    for (int d = 0; d < 512; d++) { float v = e[d]; s += v * v; }
    e2[k] = s;
}

__global__ __launch_bounds__(128)
void argmin_kernel(const float* __restrict__ z, const float* __restrict__ embed,
                   const float* __restrict__ e2, int* __restrict__ idx_out)
{
    __shared__ float z_s[512][8];
    __shared__ float rv[8][128];
    __shared__ int   ri[8][128];
    const int tid = threadIdx.x;
    const int n0 = blockIdx.x * 8;
    const int b = n0 >> 8;
    const int pix0 = n0 & 255;
    const float* zb = z + (long)b * 512 * 256 + pix0;

    for (int i = tid; i < 512 * 8; i += 128) {
        int d = i >> 3, nl = i & 7;
        z_s[d][nl] = zb[(long)d * 256 + nl];
    }
    __syncthreads();

    float bv[8]; int bi[8];
    #pragma unroll
    for (int nl = 0; nl < 8; nl++) { bv[nl] = 3.4e38f; bi[nl] = 0; }

    for (int k = tid; k < 1024; k += 128) {
        const float* e = embed + (long)k * 512;
        float dot[8];
        #pragma unroll
        for (int nl = 0; nl < 8; nl++) dot[nl] = 0.f;
        #pragma unroll 4
        for (int d = 0; d < 512; d++) {
            float evv = e[d];
            #pragma unroll
            for (int nl = 0; nl < 8; nl++) dot[nl] += evv * z_s[d][nl];
        }
        float c = e2[k];
        #pragma unroll
        for (int nl = 0; nl < 8; nl++) {
            float dist = c - 2.f * dot[nl];
            if (dist < bv[nl]) { bv[nl] = dist; bi[nl] = k; }
        }
    }
    #pragma unroll
    for (int nl = 0; nl < 8; nl++) { rv[nl][tid] = bv[nl]; ri[nl][tid] = bi[nl]; }
    __syncthreads();
    if (tid < 8) {
        float best = rv[tid][0]; int besti = ri[tid][0];
        for (int j = 1; j < 128; j++) {
            float v = rv[tid][j]; int ii = ri[tid][j];
            if (v < best || (v == best && ii < besti)) { best = v; besti = ii; }
        }
        idx_out[n0 + tid] = besti;
    }
}

__global__ void gather_kernel(const int* __restrict__ idx, const float* __restrict__ embed,
                              float* __restrict__ zq)
{
    const int n = blockIdx.x;
    const int b = n >> 8, pix = n & 255;
    const float* e = embed + (long)idx[n] * 512;
    float* o = zq + (long)b * 512 * 256 + pix;
    for (int d = threadIdx.x; d < 512; d += 256)
        o[(long)d * 256] = e[d];
}

// ---------------------------------------------------------------------------
// Launch
// ---------------------------------------------------------------------------
extern "C" void kernel_launch(void* const* d_in, const int* in_sizes, int n_in,
                              void* d_out, int out_size)
{
    const float* x     = (const float*)d_in[0];
    const float* ew1   = (const float*)d_in[1];
    const float* eb1   = (const float*)d_in[2];
    const float* ew2   = (const float*)d_in[3];
    const float* eb2   = (const float*)d_in[4];
    const float* ew3   = (const float*)d_in[5];
    const float* eb3   = (const float*)d_in[6];
    const float* ew4   = (const float*)d_in[7];
    const float* eb4   = (const float*)d_in[8];
    const float* dw1   = (const float*)d_in[9];
    const float* db1   = (const float*)d_in[10];
    const float* dw2   = (const float*)d_in[11];
    const float* db2   = (const float*)d_in[12];
    const float* dw3   = (const float*)d_in[13];
    const float* db3   = (const float*)d_in[14];
    const float* dw4   = (const float*)d_in[15];
    const float* db4   = (const float*)d_in[16];
    const float* embed = (const float*)d_in[17];
    float* out = (float*)d_out;

    float *A, *B, *e2p; int* idxp;
    cudaGetSymbolAddress((void**)&A,    g_bufA);
    cudaGetSymbolAddress((void**)&B,    g_bufB);
    cudaGetSymbolAddress((void**)&e2p,  g_e2);
    cudaGetSymbolAddress((void**)&idxp, g_idx);

    const int NB = 32;

    // ---- encoder ----
    // e1: (3,256,256)->(64,128,128): tiles 4x32, couts 2
    conv_enc<32,4,4><<<dim3(128, 2, NB), 256>>>(x,  ew1, eb1, A, 3,   256, 256, 64);
    // e2: (64,128,128)->(128,64,64): tiles 2x16, couts 4
    conv_enc<32,4,8><<<dim3(32, 4, NB), 256>>>(A,  ew2, eb2, B, 64,  128, 128, 128);
    // e3: (128,64,64)->(256,32,32): tiles 1x8, couts 8
    conv_enc<32,4,8><<<dim3(8,  8, NB), 256>>>(B,  ew3, eb3, A, 128, 64,  64,  256);
    // e4: (256,32,32)->(512,16,16): tiles 1x2, couts 16
    conv_enc<16,8,8><<<dim3(2, 16, NB), 256>>>(A,  ew4, eb4, B, 256, 32,  32,  512);

    // ---- quantizer ----
    e2_kernel<<<4, 256>>>(embed, e2p);
    argmin_kernel<<<1024, 128>>>(B, embed, e2p, idxp);
    gather_kernel<<<8192, 256>>>(idxp, embed, A);          // zq in A

    // ---- decoder ----
    // d1: (512,16,16)->(128,32,32): rowb 4, colb 1, couts 4
    convt<16,8><<<dim3(4,  4, NB), 256>>>(A, dw1, db1, B, 512, 16,  16,  128);
    // d2: (128,32,32)->(64,64,64): rowb 16, colb 1, couts 2
    convt<32,8><<<dim3(16, 2, NB), 256>>>(B, dw2, db2, A, 128, 32,  32,  64);
    // d3: (64,64,64)->(32,128,128): rowb 32, colb 2, couts 1
    convt<32,8><<<dim3(64, 1, NB), 256>>>(A, dw3, db3, B, 64,  64,  64,  32);
    // d4: (32,128,128)->(3,256,256) + tanh
    convt_final_kernel<<<dim3(256, 1, NB), 256>>>(B, dw4, db4, out);
}